// round 6
// baseline (speedup 1.0000x reference)
#include <cuda_runtime.h>
#include <cstddef>

#define KP1 6
#define KSEL 5
#define NUM_USERS 20000
#define ROW4 (NUM_USERS / 4)       // 5000 float4 groups
#define EMBED_DIM 64
#define ALPHA_F 0.7f
#define NTHREADS 256
#define NWARPS (NTHREADS / 32)
#define CAP 1024

struct __align__(8) VI { float v; int i; };

__device__ __forceinline__ bool better(float av, int ai, float bv, int bi) {
    // jax.lax.top_k order: descending value, ties -> lower index first.
    return (av > bv) || (av == bv && ai < bi);
}

__device__ __forceinline__ void exact_insert(VI best[KP1], float v, int idx) {
    if (better(v, idx, best[KP1 - 1].v, best[KP1 - 1].i)) {
        best[KP1 - 1].v = v;
        best[KP1 - 1].i = idx;
        #pragma unroll
        for (int j = KP1 - 1; j > 0; j--) {
            if (better(best[j].v, best[j].i, best[j - 1].v, best[j - 1].i)) {
                VI tmp = best[j]; best[j] = best[j - 1]; best[j - 1] = tmp;
            }
        }
    }
}

__device__ __forceinline__ float fmax4(float4 f) {
    return fmaxf(fmaxf(f.x, f.y), fmaxf(f.z, f.w));
}

__device__ __forceinline__ void emit4(float4 f, int base, float T,
                                      int* s_count, float* s_cval, int* s_cidx) {
    if (f.x >= T) { int p = atomicAdd(s_count, 1); if (p < CAP) { s_cval[p] = f.x; s_cidx[p] = base + 0; } }
    if (f.y >= T) { int p = atomicAdd(s_count, 1); if (p < CAP) { s_cval[p] = f.y; s_cidx[p] = base + 1; } }
    if (f.z >= T) { int p = atomicAdd(s_count, 1); if (p < CAP) { s_cval[p] = f.z; s_cidx[p] = base + 2; } }
    if (f.w >= T) { int p = atomicAdd(s_count, 1); if (p < CAP) { s_cval[p] = f.w; s_cidx[p] = base + 3; } }
}

__global__ __launch_bounds__(NTHREADS)
void user_blend_kernel(const int* __restrict__ user_idx,
                       const float* __restrict__ emb,
                       const float* __restrict__ cooc,
                       float* __restrict__ out)
{
    __shared__ float s_wmax[NWARPS];
    __shared__ float s_cval[CAP];
    __shared__ int   s_cidx[CAP];
    __shared__ int   s_count;
    __shared__ float s_w[KSEL];
    __shared__ int   s_idx[KSEL];

    const int t = threadIdx.x;
    const int lane = t & 31;
    const int warp = t >> 5;
    const int u = user_idx[blockIdx.x];
    const float4* __restrict__ row4 =
        reinterpret_cast<const float4*>(cooc + (size_t)u * NUM_USERS);

    // ---------- Phase 0: threshold from the first 4096 elements ----------
    // These 4 loads double as the first main-loop batch: kept in registers,
    // filtered after T is known (no re-read).
    float4 p0 = row4[t];
    float4 p1 = row4[t + NTHREADS];
    float4 p2 = row4[t + 2 * NTHREADS];
    float4 p3 = row4[t + 3 * NTHREADS];
    {
        float pm = fmaxf(fmaxf(fmax4(p0), fmax4(p1)), fmaxf(fmax4(p2), fmax4(p3)));
        #pragma unroll
        for (int s = 16; s >= 1; s >>= 1)
            pm = fmaxf(pm, __shfl_xor_sync(0xffffffffu, pm, s));
        if (lane == 0) s_wmax[warp] = pm;
        if (t == 0) s_count = 0;
    }
    __syncthreads();

    // Every thread redundantly computes T = 6th-largest of the 8 warp maxes.
    // Safe lower bound: the 6 largest warp-maxes are 6 distinct row elements,
    // so T <= true 6th-largest of the row. Filter with >= preserves exactness.
    float T;
    {
        float top[KP1];
        #pragma unroll
        for (int j = 0; j < KP1; j++) top[j] = -3.0e38f;
        #pragma unroll
        for (int k = 0; k < NWARPS; k++) {
            float v = s_wmax[k];   // broadcast read
            #pragma unroll
            for (int j = 0; j < KP1; j++) {
                float lo = fminf(top[j], v);
                top[j]   = fmaxf(top[j], v);
                v = lo;
            }
        }
        T = top[KP1 - 1];
    }

    // Filter the prefix batch already in registers.
    {
        float bm = fmaxf(fmaxf(fmax4(p0), fmax4(p1)), fmaxf(fmax4(p2), fmax4(p3)));
        if (bm >= T) {
            emit4(p0, t * 4,                   T, &s_count, s_cval, s_cidx);
            emit4(p1, (t + NTHREADS) * 4,      T, &s_count, s_cval, s_cidx);
            emit4(p2, (t + 2 * NTHREADS) * 4,  T, &s_count, s_cval, s_cidx);
            emit4(p3, (t + 3 * NTHREADS) * 4,  T, &s_count, s_cval, s_cidx);
        }
    }

    // ---------- Phase 1: remaining row, 8-deep batched loads (MLP=8) ----------
    int i = t + 4 * NTHREADS;
    for (; i + 7 * NTHREADS < ROW4; i += 8 * NTHREADS) {
        float4 a = row4[i];
        float4 b = row4[i + NTHREADS];
        float4 c = row4[i + 2 * NTHREADS];
        float4 d = row4[i + 3 * NTHREADS];
        float4 e = row4[i + 4 * NTHREADS];
        float4 f = row4[i + 5 * NTHREADS];
        float4 g = row4[i + 6 * NTHREADS];
        float4 h = row4[i + 7 * NTHREADS];
        float m01 = fmaxf(fmax4(a), fmax4(b));
        float m23 = fmaxf(fmax4(c), fmax4(d));
        float m45 = fmaxf(fmax4(e), fmax4(f));
        float m67 = fmaxf(fmax4(g), fmax4(h));
        float bm = fmaxf(fmaxf(m01, m23), fmaxf(m45, m67));
        if (bm >= T) {                 // rare
            emit4(a, i * 4,                   T, &s_count, s_cval, s_cidx);
            emit4(b, (i + NTHREADS) * 4,      T, &s_count, s_cval, s_cidx);
            emit4(c, (i + 2 * NTHREADS) * 4,  T, &s_count, s_cval, s_cidx);
            emit4(d, (i + 3 * NTHREADS) * 4,  T, &s_count, s_cval, s_cidx);
            emit4(e, (i + 4 * NTHREADS) * 4,  T, &s_count, s_cval, s_cidx);
            emit4(f, (i + 5 * NTHREADS) * 4,  T, &s_count, s_cval, s_cidx);
            emit4(g, (i + 6 * NTHREADS) * 4,  T, &s_count, s_cval, s_cidx);
            emit4(h, (i + 7 * NTHREADS) * 4,  T, &s_count, s_cval, s_cidx);
        }
    }
    for (; i + 3 * NTHREADS < ROW4; i += 4 * NTHREADS) {
        float4 a = row4[i];
        float4 b = row4[i + NTHREADS];
        float4 c = row4[i + 2 * NTHREADS];
        float4 d = row4[i + 3 * NTHREADS];
        float bm = fmaxf(fmaxf(fmax4(a), fmax4(b)), fmaxf(fmax4(c), fmax4(d)));
        if (bm >= T) {
            emit4(a, i * 4,                   T, &s_count, s_cval, s_cidx);
            emit4(b, (i + NTHREADS) * 4,      T, &s_count, s_cval, s_cidx);
            emit4(c, (i + 2 * NTHREADS) * 4,  T, &s_count, s_cval, s_cidx);
            emit4(d, (i + 3 * NTHREADS) * 4,  T, &s_count, s_cval, s_cidx);
        }
    }
    for (; i < ROW4; i += NTHREADS) {
        float4 a = row4[i];
        if (fmax4(a) >= T)
            emit4(a, i * 4, T, &s_count, s_cval, s_cidx);
    }
    __syncthreads();

    // ---------- Final exact top-6, softmax, weights ----------
    if (t == 0) {
        VI best[KP1];
        #pragma unroll
        for (int j = 0; j < KP1; j++) { best[j].v = -3.0e38f; best[j].i = 0x7fffffff; }

        int cnt = s_count;
        if (cnt <= CAP) {
            for (int k = 0; k < cnt; k++)
                exact_insert(best, s_cval[k], s_cidx[k]);
        } else {
            // Overflow fallback (adversarial ties only): serial exact scan.
            const float* row = cooc + (size_t)u * NUM_USERS;
            for (int k = 0; k < NUM_USERS; k++)
                exact_insert(best, row[k], k);
        }

        // Drop slot 0 (the max), softmax over slots 1..5.
        float m = best[1].v;
        float e[KSEL];
        float sum = 0.0f;
        #pragma unroll
        for (int j = 0; j < KSEL; j++) {
            e[j] = __expf(best[j + 1].v - m);
            sum += e[j];
        }
        float inv = 1.0f / sum;
        #pragma unroll
        for (int j = 0; j < KSEL; j++) {
            s_w[j]   = e[j] * inv;
            s_idx[j] = best[j + 1].i;
        }
    }
    __syncthreads();

    // ---------- Blend ----------
    if (t < EMBED_DIM) {
        float acc = 0.0f;
        #pragma unroll
        for (int j = 0; j < KSEL; j++)
            acc += s_w[j] * emb[(size_t)s_idx[j] * EMBED_DIM + t];
        float self = emb[(size_t)u * EMBED_DIM + t];
        out[(size_t)blockIdx.x * EMBED_DIM + t] = ALPHA_F * self + (1.0f - ALPHA_F) * acc;
    }
}

extern "C" void kernel_launch(void* const* d_in, const int* in_sizes, int n_in,
                              void* d_out, int out_size)
{
    // Identify inputs by element count:
    //   user_idx: 4096 (int32), emb: 20000*64 (f32), cooc: 20000*20000 (f32)
    const int*   user_idx = nullptr;
    const float* emb      = nullptr;
    const float* cooc     = nullptr;
    int batch = 0;
    for (int i = 0; i < n_in; i++) {
        long long sz = in_sizes[i];
        if (sz == (long long)NUM_USERS * NUM_USERS) {
            cooc = (const float*)d_in[i];
        } else if (sz == (long long)NUM_USERS * EMBED_DIM) {
            emb = (const float*)d_in[i];
        } else {
            user_idx = (const int*)d_in[i];
            batch = (int)sz;
        }
    }
    float* out = (float*)d_out;
    user_blend_kernel<<<batch, NTHREADS>>>(user_idx, emb, cooc, out);
}

// round 8
// speedup vs baseline: 1.3251x; 1.3251x over previous
#include <cuda_runtime.h>
#include <cstddef>

#define KP1 6
#define KSEL 5
#define NUM_USERS 20000
#define ROW4 (NUM_USERS / 4)       // 5000 float4 groups
#define EMBED_DIM 64
#define ALPHA_F 0.7f
#define NTHREADS 256
#define NWARPS (NTHREADS / 32)
#define NBATCH 5                   // ceil(5000 / (4*256)) batches of 4-deep loads
#define CAP 1024

struct __align__(8) VI { float v; int i; };

__device__ __forceinline__ bool better(float av, int ai, float bv, int bi) {
    // jax.lax.top_k order: descending value, ties -> lower index first.
    return (av > bv) || (av == bv && ai < bi);
}

__device__ __forceinline__ void exact_insert(VI best[KP1], float v, int idx) {
    if (better(v, idx, best[KP1 - 1].v, best[KP1 - 1].i)) {
        best[KP1 - 1].v = v;
        best[KP1 - 1].i = idx;
        #pragma unroll
        for (int j = KP1 - 1; j > 0; j--) {
            if (better(best[j].v, best[j].i, best[j - 1].v, best[j - 1].i)) {
                VI tmp = best[j]; best[j] = best[j - 1]; best[j - 1] = tmp;
            }
        }
    }
}

__device__ __forceinline__ float fmax4(float4 f) {
    return fmaxf(fmaxf(f.x, f.y), fmaxf(f.z, f.w));
}

__device__ __forceinline__ void emit4(float4 f, int base, float T,
                                      int* s_count, float* s_cval, int* s_cidx) {
    if (f.x >= T) { int p = atomicAdd(s_count, 1); if (p < CAP) { s_cval[p] = f.x; s_cidx[p] = base + 0; } }
    if (f.y >= T) { int p = atomicAdd(s_count, 1); if (p < CAP) { s_cval[p] = f.y; s_cidx[p] = base + 1; } }
    if (f.z >= T) { int p = atomicAdd(s_count, 1); if (p < CAP) { s_cval[p] = f.z; s_cidx[p] = base + 2; } }
    if (f.w >= T) { int p = atomicAdd(s_count, 1); if (p < CAP) { s_cval[p] = f.w; s_cidx[p] = base + 3; } }
}

__global__ __launch_bounds__(NTHREADS, 7)
void user_blend_kernel(const int* __restrict__ user_idx,
                       const float* __restrict__ emb,
                       const float* __restrict__ cooc,
                       float* __restrict__ out)
{
    __shared__ float s_wmax[NWARPS];
    __shared__ float s_cval[CAP];
    __shared__ int   s_cidx[CAP];
    __shared__ int   s_count;
    __shared__ float s_w[KSEL];
    __shared__ int   s_idx[KSEL];

    const int t = threadIdx.x;
    const int lane = t & 31;
    const int warp = t >> 5;
    const int u = user_idx[blockIdx.x];
    const float4* __restrict__ row4 =
        reinterpret_cast<const float4*>(cooc + (size_t)u * NUM_USERS);

    // ---------- Phase 0: threshold from the first 4096 elements ----------
    {
        float4 a = row4[t];
        float4 b = row4[t + NTHREADS];
        float4 c = row4[t + 2 * NTHREADS];
        float4 d = row4[t + 3 * NTHREADS];
        float pm = fmaxf(fmaxf(fmax4(a), fmax4(b)), fmaxf(fmax4(c), fmax4(d)));
        #pragma unroll
        for (int s = 16; s >= 1; s >>= 1)
            pm = fmaxf(pm, __shfl_xor_sync(0xffffffffu, pm, s));
        if (lane == 0) s_wmax[warp] = pm;
        if (t == 0) s_count = 0;
    }
    __syncthreads();

    // Every thread redundantly computes T = 6th-largest of the 8 warp maxes.
    // Safe lower bound: the 6 largest warp-maxes are >=6 distinct row elements,
    // so T <= true 6th-largest of the row. Filter with >= preserves exactness.
    float T;
    {
        float top[KP1];
        #pragma unroll
        for (int j = 0; j < KP1; j++) top[j] = -3.0e38f;
        #pragma unroll
        for (int k = 0; k < NWARPS; k++) {
            float v = s_wmax[k];   // broadcast read
            #pragma unroll
            for (int j = 0; j < KP1; j++) {
                float lo = fminf(top[j], v);
                top[j]   = fmaxf(top[j], v);
                v = lo;
            }
        }
        T = top[KP1 - 1];
    }

    // ---------- Phase 1: full row, uniform 4-deep batches (MLP=4) ----------
    // 5 batches cover 5*4*256 = 5120 >= 5000 groups; out-of-range lanes use
    // clamped (in-bounds) loads and are masked out of the filter.
    #pragma unroll 1
    for (int b = 0; b < NBATCH; b++) {
        int i0 = t + b * 4 * NTHREADS;
        int i1 = i0 + NTHREADS;
        int i2 = i0 + 2 * NTHREADS;
        int i3 = i0 + 3 * NTHREADS;
        float4 a = row4[min(i0, ROW4 - 1)];
        float4 c = row4[min(i1, ROW4 - 1)];
        float4 d = row4[min(i2, ROW4 - 1)];
        float4 e = row4[min(i3, ROW4 - 1)];
        float ma = (i0 < ROW4) ? fmax4(a) : -3.0e38f;
        float mc = (i1 < ROW4) ? fmax4(c) : -3.0e38f;
        float md = (i2 < ROW4) ? fmax4(d) : -3.0e38f;
        float me = (i3 < ROW4) ? fmax4(e) : -3.0e38f;
        float bm = fmaxf(fmaxf(ma, mc), fmaxf(md, me));
        if (bm >= T) {                 // rare (~few % of thread-batches)
            if (ma >= T) emit4(a, i0 * 4, T, &s_count, s_cval, s_cidx);
            if (mc >= T) emit4(c, i1 * 4, T, &s_count, s_cval, s_cidx);
            if (md >= T) emit4(d, i2 * 4, T, &s_count, s_cval, s_cidx);
            if (me >= T) emit4(e, i3 * 4, T, &s_count, s_cval, s_cidx);
        }
    }
    __syncthreads();

    // ---------- Final exact top-6, softmax, weights ----------
    if (t == 0) {
        VI best[KP1];
        #pragma unroll
        for (int j = 0; j < KP1; j++) { best[j].v = -3.0e38f; best[j].i = 0x7fffffff; }

        int cnt = s_count;
        if (cnt <= CAP) {
            for (int k = 0; k < cnt; k++)
                exact_insert(best, s_cval[k], s_cidx[k]);
        } else {
            // Overflow fallback (adversarial ties only): serial exact scan.
            const float* row = cooc + (size_t)u * NUM_USERS;
            for (int k = 0; k < NUM_USERS; k++)
                exact_insert(best, row[k], k);
        }

        // Drop slot 0 (the max), softmax over slots 1..5.
        float m = best[1].v;
        float e[KSEL];
        float sum = 0.0f;
        #pragma unroll
        for (int j = 0; j < KSEL; j++) {
            e[j] = __expf(best[j + 1].v - m);
            sum += e[j];
        }
        float inv = 1.0f / sum;
        #pragma unroll
        for (int j = 0; j < KSEL; j++) {
            s_w[j]   = e[j] * inv;
            s_idx[j] = best[j + 1].i;
        }
    }
    __syncthreads();

    // ---------- Blend ----------
    if (t < EMBED_DIM) {
        float acc = 0.0f;
        #pragma unroll
        for (int j = 0; j < KSEL; j++)
            acc += s_w[j] * emb[(size_t)s_idx[j] * EMBED_DIM + t];
        float self = emb[(size_t)u * EMBED_DIM + t];
        out[(size_t)blockIdx.x * EMBED_DIM + t] = ALPHA_F * self + (1.0f - ALPHA_F) * acc;
    }
}

extern "C" void kernel_launch(void* const* d_in, const int* in_sizes, int n_in,
                              void* d_out, int out_size)
{
    // Identify inputs by element count:
    //   user_idx: 4096 (int32), emb: 20000*64 (f32), cooc: 20000*20000 (f32)
    const int*   user_idx = nullptr;
    const float* emb      = nullptr;
    const float* cooc     = nullptr;
    int batch = 0;
    for (int i = 0; i < n_in; i++) {
        long long sz = in_sizes[i];
        if (sz == (long long)NUM_USERS * NUM_USERS) {
            cooc = (const float*)d_in[i];
        } else if (sz == (long long)NUM_USERS * EMBED_DIM) {
            emb = (const float*)d_in[i];
        } else {
            user_idx = (const int*)d_in[i];
            batch = (int)sz;
        }
    }
    float* out = (float*)d_out;
    user_blend_kernel<<<batch, NTHREADS>>>(user_idx, emb, cooc, out);
}

// round 9
// speedup vs baseline: 1.3587x; 1.0253x over previous
#include <cuda_runtime.h>
#include <cstddef>

#define KP1 6
#define KSEL 5
#define NUM_USERS 20000
#define ROW4 (NUM_USERS / 4)       // 5000 float4 groups
#define EMBED_DIM 64
#define ALPHA_F 0.7f
#define NTHREADS 256
#define NWARPS (NTHREADS / 32)
#define CAP 1024

struct __align__(8) VI { float v; int i; };

__device__ __forceinline__ bool better(float av, int ai, float bv, int bi) {
    // jax.lax.top_k order: descending value, ties -> lower index first.
    return (av > bv) || (av == bv && ai < bi);
}

__device__ __forceinline__ void exact_insert(VI best[KP1], float v, int idx) {
    if (better(v, idx, best[KP1 - 1].v, best[KP1 - 1].i)) {
        best[KP1 - 1].v = v;
        best[KP1 - 1].i = idx;
        #pragma unroll
        for (int j = KP1 - 1; j > 0; j--) {
            if (better(best[j].v, best[j].i, best[j - 1].v, best[j - 1].i)) {
                VI tmp = best[j]; best[j] = best[j - 1]; best[j - 1] = tmp;
            }
        }
    }
}

__device__ __forceinline__ float fmax4(float4 f) {
    return fmaxf(fmaxf(f.x, f.y), fmaxf(f.z, f.w));
}

__device__ __forceinline__ void emit4(float4 f, int base, float T,
                                      int* s_count, float* s_cval, int* s_cidx) {
    if (f.x >= T) { int p = atomicAdd(s_count, 1); if (p < CAP) { s_cval[p] = f.x; s_cidx[p] = base + 0; } }
    if (f.y >= T) { int p = atomicAdd(s_count, 1); if (p < CAP) { s_cval[p] = f.y; s_cidx[p] = base + 1; } }
    if (f.z >= T) { int p = atomicAdd(s_count, 1); if (p < CAP) { s_cval[p] = f.z; s_cidx[p] = base + 2; } }
    if (f.w >= T) { int p = atomicAdd(s_count, 1); if (p < CAP) { s_cval[p] = f.w; s_cidx[p] = base + 3; } }
}

__global__ __launch_bounds__(NTHREADS, 7)
void user_blend_kernel(const int* __restrict__ user_idx,
                       const float* __restrict__ emb,
                       const float* __restrict__ cooc,
                       float* __restrict__ out)
{
    __shared__ float s_wmax[NWARPS];
    __shared__ float s_cval[CAP];
    __shared__ int   s_cidx[CAP];
    __shared__ int   s_count;
    __shared__ float s_w[KSEL];
    __shared__ int   s_idx[KSEL];

    const int t = threadIdx.x;
    const int lane = t & 31;
    const int warp = t >> 5;
    const int u = user_idx[blockIdx.x];
    const float4* __restrict__ row4 =
        reinterpret_cast<const float4*>(cooc + (size_t)u * NUM_USERS);

    // ---------- Phase 0: threshold from the first 4096 elements ----------
    {
        float4 a = row4[t];
        float4 b = row4[t + NTHREADS];
        float4 c = row4[t + 2 * NTHREADS];
        float4 d = row4[t + 3 * NTHREADS];
        float pm = fmaxf(fmaxf(fmax4(a), fmax4(b)), fmaxf(fmax4(c), fmax4(d)));
        #pragma unroll
        for (int s = 16; s >= 1; s >>= 1)
            pm = fmaxf(pm, __shfl_xor_sync(0xffffffffu, pm, s));
        if (lane == 0) s_wmax[warp] = pm;
        if (t == 0) s_count = 0;
    }
    __syncthreads();

    // Every thread redundantly computes T = 6th-largest of the 8 warp maxes.
    // Safe lower bound: the 6 largest warp-maxes are >=6 distinct row elements,
    // so T <= true 6th-largest of the row. Filter with >= preserves exactness.
    float T;
    {
        float top[KP1];
        #pragma unroll
        for (int j = 0; j < KP1; j++) top[j] = -3.0e38f;
        #pragma unroll
        for (int k = 0; k < NWARPS; k++) {
            float v = s_wmax[k];   // broadcast read
            #pragma unroll
            for (int j = 0; j < KP1; j++) {
                float lo = fminf(top[j], v);
                top[j]   = fmaxf(top[j], v);
                v = lo;
            }
        }
        T = top[KP1 - 1];
    }

    // ---------- Phase 1a: groups 0..4095, unclamped 4-deep batches ----------
    #pragma unroll 1
    for (int b = 0; b < 4; b++) {
        int i0 = t + b * 4 * NTHREADS;
        float4 a = row4[i0];
        float4 c = row4[i0 + NTHREADS];
        float4 d = row4[i0 + 2 * NTHREADS];
        float4 e = row4[i0 + 3 * NTHREADS];
        float ma = fmax4(a);
        float mc = fmax4(c);
        float md = fmax4(d);
        float me = fmax4(e);
        float bm = fmaxf(fmaxf(ma, mc), fmaxf(md, me));
        if (bm >= T) {                 // rare
            if (ma >= T) emit4(a, i0 * 4,                  T, &s_count, s_cval, s_cidx);
            if (mc >= T) emit4(c, (i0 + NTHREADS) * 4,     T, &s_count, s_cval, s_cidx);
            if (md >= T) emit4(d, (i0 + 2 * NTHREADS) * 4, T, &s_count, s_cval, s_cidx);
            if (me >= T) emit4(e, (i0 + 3 * NTHREADS) * 4, T, &s_count, s_cval, s_cidx);
        }
    }

    // ---------- Phase 1b: tail groups 4096..4999 (the only clamped batch) ----------
    {
        int i0 = t + 4 * 4 * NTHREADS;          // 4096 + t
        int i1 = i0 + NTHREADS;
        int i2 = i0 + 2 * NTHREADS;
        int i3 = i0 + 3 * NTHREADS;
        float4 a = row4[min(i0, ROW4 - 1)];
        float4 c = row4[min(i1, ROW4 - 1)];
        float4 d = row4[min(i2, ROW4 - 1)];
        float4 e = row4[min(i3, ROW4 - 1)];
        float ma = (i0 < ROW4) ? fmax4(a) : -3.0e38f;
        float mc = (i1 < ROW4) ? fmax4(c) : -3.0e38f;
        float md = (i2 < ROW4) ? fmax4(d) : -3.0e38f;
        float me = (i3 < ROW4) ? fmax4(e) : -3.0e38f;
        float bm = fmaxf(fmaxf(ma, mc), fmaxf(md, me));
        if (bm >= T) {
            if (ma >= T) emit4(a, i0 * 4, T, &s_count, s_cval, s_cidx);
            if (mc >= T) emit4(c, i1 * 4, T, &s_count, s_cval, s_cidx);
            if (md >= T) emit4(d, i2 * 4, T, &s_count, s_cval, s_cidx);
            if (me >= T) emit4(e, i3 * 4, T, &s_count, s_cval, s_cidx);
        }
    }
    __syncthreads();

    // ---------- Final exact top-6, softmax, weights ----------
    if (t == 0) {
        VI best[KP1];
        #pragma unroll
        for (int j = 0; j < KP1; j++) { best[j].v = -3.0e38f; best[j].i = 0x7fffffff; }

        int cnt = s_count;
        if (cnt <= CAP) {
            for (int k = 0; k < cnt; k++)
                exact_insert(best, s_cval[k], s_cidx[k]);
        } else {
            // Overflow fallback (adversarial ties only): serial exact scan.
            const float* row = cooc + (size_t)u * NUM_USERS;
            for (int k = 0; k < NUM_USERS; k++)
                exact_insert(best, row[k], k);
        }

        // Drop slot 0 (the max), softmax over slots 1..5.
        float m = best[1].v;
        float e[KSEL];
        float sum = 0.0f;
        #pragma unroll
        for (int j = 0; j < KSEL; j++) {
            e[j] = __expf(best[j + 1].v - m);
            sum += e[j];
        }
        float inv = 1.0f / sum;
        #pragma unroll
        for (int j = 0; j < KSEL; j++) {
            s_w[j]   = e[j] * inv;
            s_idx[j] = best[j + 1].i;
        }
    }
    __syncthreads();

    // ---------- Blend ----------
    if (t < EMBED_DIM) {
        float acc = 0.0f;
        #pragma unroll
        for (int j = 0; j < KSEL; j++)
            acc += s_w[j] * emb[(size_t)s_idx[j] * EMBED_DIM + t];
        float self = emb[(size_t)u * EMBED_DIM + t];
        out[(size_t)blockIdx.x * EMBED_DIM + t] = ALPHA_F * self + (1.0f - ALPHA_F) * acc;
    }
}

extern "C" void kernel_launch(void* const* d_in, const int* in_sizes, int n_in,
                              void* d_out, int out_size)
{
    // Identify inputs by element count:
    //   user_idx: 4096 (int32), emb: 20000*64 (f32), cooc: 20000*20000 (f32)
    const int*   user_idx = nullptr;
    const float* emb      = nullptr;
    const float* cooc     = nullptr;
    int batch = 0;
    for (int i = 0; i < n_in; i++) {
        long long sz = in_sizes[i];
        if (sz == (long long)NUM_USERS * NUM_USERS) {
            cooc = (const float*)d_in[i];
        } else if (sz == (long long)NUM_USERS * EMBED_DIM) {
            emb = (const float*)d_in[i];
        } else {
            user_idx = (const int*)d_in[i];
            batch = (int)sz;
        }
    }
    float* out = (float*)d_out;
    user_blend_kernel<<<batch, NTHREADS>>>(user_idx, emb, cooc, out);
}